// round 8
// baseline (speedup 1.0000x reference)
#include <cuda_runtime.h>
#include <cuda_fp16.h>
#include <cstdint>

// ===========================================================================
// GRUConv3d, single-pass fp16 HMMA GEMM:
//  GEMM block tile 128x256, warp tile 64x64 (2x4 warps), 4-stage cp.async.
//  scan: 8 dirs, affine diagonal chains, distance-2 software pipeline.
// ===========================================================================

#define NB 2
#define NSP 32768
#define NROW 65536
#define KDIM 864            // 32ci * 27taps = 54 * 16
#define MTOT 768            // 8 dir * 3 gate * 32 co

__device__ __align__(16) __half g_Bh[(size_t)NROW * KDIM];
__device__ __align__(16) __half g_Wh[(size_t)MTOT * KDIM];
__device__ __align__(16) float  g_C[(size_t)MTOT * NROW];
__device__ float                g_bias[MTOT];

// ---------------- helpers ---------------------------------------------------
__device__ __forceinline__ uint32_t smem_u32(const void* p) {
    uint32_t a;
    asm("{ .reg .u64 t; cvta.to.shared.u64 t, %1; cvt.u32.u64 %0, t; }" : "=r"(a) : "l"(p));
    return a;
}
__device__ __forceinline__ void cp16(uint32_t dst, const void* src) {
    asm volatile("cp.async.cg.shared.global [%0], [%1], 16;" :: "r"(dst), "l"(src));
}
#define CP_COMMIT() asm volatile("cp.async.commit_group;" ::: "memory")
#define CP_WAIT(n)  asm volatile("cp.async.wait_group %0;" :: "n"(n) : "memory")

#define LDSM4(r, a) \
    asm volatile("ldmatrix.sync.aligned.m8n8.x4.shared.b16 {%0,%1,%2,%3}, [%4];" \
                 : "=r"((r)[0]), "=r"((r)[1]), "=r"((r)[2]), "=r"((r)[3]) : "r"(a))

#define MMA16816(c, a, b0, b1) \
    asm volatile("mma.sync.aligned.m16n8k16.row.col.f32.f16.f16.f32 " \
                 "{%0,%1,%2,%3}, {%4,%5,%6,%7}, {%8,%9}, {%0,%1,%2,%3};" \
                 : "+f"((c)[0]), "+f"((c)[1]), "+f"((c)[2]), "+f"((c)[3]) \
                 : "r"((a)[0]), "r"((a)[1]), "r"((a)[2]), "r"((a)[3]), \
                   "r"(b0), "r"(b1))

// ---------------- 1) weight prep --------------------------------------------
__global__ void wprep_kernel(const float* __restrict__ Wh, const float* __restrict__ bh,
                             const float* __restrict__ Wz, const float* __restrict__ bz,
                             const float* __restrict__ Ws, const float* __restrict__ bs)
{
    const int m = blockIdx.x;
    const int n = m / 96, r = m % 96, g = r >> 5, co = r & 31;
    const float* Wp = (g == 0) ? Wh : ((g == 1) ? Wz : Ws);
    const float* bp = (g == 0) ? bh : ((g == 1) ? bz : bs);
    if (threadIdx.x == 0) g_bias[m] = bp[n * 32 + co];
    for (int k = threadIdx.x; k < KDIM; k += blockDim.x) {
        int ci = k / 27, t = k % 27;
        g_Wh[(size_t)m * KDIM + k] =
            __float2half(Wp[((n * 32 + co) * 32 + ci) * 27 + t]);
    }
}

// ---------------- 2) im2col --------------------------------------------------
#define I2C_STRIDE 904
#define I2C_SMEM (32 * I2C_STRIDE * 2)
__global__ void __launch_bounds__(256)
im2col_kernel(const float* __restrict__ x)
{
    extern __shared__ __half sm2[];
    const int tid = threadIdx.x, lane = tid & 31, wi = tid >> 5;
    const int bid = blockIdx.x;
    const int b = bid >> 10, d = (bid >> 5) & 31, h = bid & 31;

    for (int k = wi; k < KDIM; k += 8) {
        int ci = k / 27, t = k % 27;
        int td = t / 9, th = (t % 9) / 3, tw = t % 3;
        int gd = d + td - 1, gh = h + th - 1, gw = lane + tw - 1;
        float v = 0.f;
        if (gd >= 0 && gd < 32 && gh >= 0 && gh < 32 && gw >= 0 && gw < 32)
            v = x[(((b * 32 + ci) * 32 + gd) * 32 + gh) * 32 + gw];
        sm2[lane * I2C_STRIDE + k] = __float2half(v);
    }
    __syncthreads();

    const size_t row0 = (size_t)b * NSP + d * 1024 + h * 32;
    const uint4* smv = (const uint4*)sm2;
    uint4* gv = (uint4*)(g_Bh + row0 * KDIM);
    const int KV = KDIM / 8;
    for (int idx = tid; idx < 32 * KV; idx += 256) {
        int w = idx / KV, kv = idx % KV;
        gv[(size_t)w * KV + kv] = smv[w * (I2C_STRIDE / 8) + kv];
    }
}

// ---------------- 3) GEMM: 128x256 block, 64x64 warp, 4 stages ---------------
#define ASTR_B 80
#define B_OFF 10240                         // A: 128*80, B: 256*80
#define STAGE_B 30720
#define NSTG 4
#define GEMM_SMEM (NSTG * STAGE_B)          // 122880
#define NKC (KDIM / 32)                     // 27

__global__ void __launch_bounds__(256, 1)
gemm_kernel()
{
    extern __shared__ __align__(16) char sm[];
    const int tid = threadIdx.x, lane = tid & 31, wid = tid >> 5;
    const int m0 = blockIdx.x * 128;
    const size_t n0 = (size_t)blockIdx.y * 256;
    const int wm = wid & 1, wn = wid >> 1;         // 2 x 4 warps
    const uint32_t sbase = smem_u32(sm);

    const char* gA = (const char*)g_Wh + (size_t)m0 * (KDIM * 2);
    const char* gB = (const char*)g_Bh + n0 * (KDIM * 2);

    float acc[4][8][4];
#pragma unroll
    for (int i = 0; i < 4; ++i)
#pragma unroll
        for (int j = 0; j < 8; ++j)
#pragma unroll
            for (int q = 0; q < 4; ++q) acc[i][j][q] = 0.f;

    const int a_row = lane & 15;
    const int a_k8  = (lane >> 4) << 3;
    const int b_row = wn * 64 + (lane & 7) + ((lane >> 4) << 3);
    const int b_k8  = ((lane >> 3) & 1) << 3;

    auto load_stage = [&](int kc, int s) {
        const int koff = kc * 64;
        const uint32_t st = sbase + s * STAGE_B;
        for (int i = tid; i < 512; i += 256) {         // A: 128 rows x 64B
            int r = i >> 2, c = (i & 3) << 4;
            cp16(st + r * ASTR_B + c, gA + (size_t)r * (KDIM * 2) + koff + c);
        }
        for (int i = tid; i < 1024; i += 256) {        // B: 256 rows x 64B
            int r = i >> 2, c = (i & 3) << 4;
            cp16(st + B_OFF + r * ASTR_B + c, gB + (size_t)r * (KDIM * 2) + koff + c);
        }
        CP_COMMIT();
    };

    auto compute = [&](int s) {
        const uint32_t st = sbase + s * STAGE_B;
#pragma unroll
        for (int ks = 0; ks < 2; ++ks) {
            uint32_t A[4][4], B[4][4];
#pragma unroll
            for (int mt2 = 0; mt2 < 4; ++mt2) {
                uint32_t a = st + (wm * 64 + mt2 * 16 + a_row) * ASTR_B
                               + (ks * 16 + a_k8) * 2;
                LDSM4(A[mt2], a);
            }
#pragma unroll
            for (int bt = 0; bt < 4; ++bt) {
                uint32_t a = st + B_OFF + (b_row + bt * 16) * ASTR_B
                               + (ks * 16 + b_k8) * 2;
                LDSM4(B[bt], a);
            }
#pragma unroll
            for (int mt2 = 0; mt2 < 4; ++mt2)
#pragma unroll
                for (int nt8 = 0; nt8 < 8; ++nt8) {
                    const uint32_t* bb = &B[nt8 >> 1][(nt8 & 1) * 2];
                    MMA16816(acc[mt2][nt8], A[mt2], bb[0], bb[1]);
                }
        }
    };

    // 4-stage pipeline, one barrier per chunk
    load_stage(0, 0);
    load_stage(1, 1);
    load_stage(2, 2);
    int s = 0;
    for (int kc = 0; kc < NKC; ++kc) {
        CP_WAIT(2);                  // stage kc arrived; kc+1, kc+2 in flight
        __syncthreads();             // all warps done with stage (kc+3)%4's old data
        if (kc + 3 < NKC) {
            int s3 = s + 3; if (s3 >= NSTG) s3 -= NSTG;
            load_stage(kc + 3, s3);
        }
        compute(s);
        if (++s == NSTG) s = 0;
    }

    // epilogue: bias + sigmoid for z/s gates, store
    const int rgrp = lane >> 2, cpair = lane & 3;
#pragma unroll
    for (int mt2 = 0; mt2 < 4; ++mt2) {
        const int mA = m0 + wm * 64 + mt2 * 16 + rgrp;
        const bool gate = ((mA >> 5) % 3) != 0;
        const float biasA = g_bias[mA];
        const float biasB = g_bias[mA + 8];
#pragma unroll
        for (int nt8 = 0; nt8 < 8; ++nt8) {
            size_t col = n0 + wn * 64 + nt8 * 8 + cpair * 2;
            float v0 = acc[mt2][nt8][0] + biasA;
            float v1 = acc[mt2][nt8][1] + biasA;
            float v2 = acc[mt2][nt8][2] + biasB;
            float v3 = acc[mt2][nt8][3] + biasB;
            if (gate) {
                v0 = 1.f / (1.f + __expf(-v0));
                v1 = 1.f / (1.f + __expf(-v1));
                v2 = 1.f / (1.f + __expf(-v2));
                v3 = 1.f / (1.f + __expf(-v3));
            }
            *(float2*)(g_C + (size_t)mA * NROW + col)       = make_float2(v0, v1);
            *(float2*)(g_C + (size_t)(mA + 8) * NROW + col) = make_float2(v2, v3);
        }
    }
}

// ---------------- 4) scan (all dirs, distance-2 pipeline) --------------------
__global__ void scan_kernel(const float* __restrict__ h0v)
{
    const int gwarp = (blockIdx.x * blockDim.x + threadIdx.x) >> 5;
    const int lane  = threadIdx.x & 31;
    const int n     = blockIdx.y;
    const int half  = gwarp & 1;
    const int d1i   = (gwarp >> 1) % 63;
    const int c     = (gwarp / 126) % 32;
    const int b     = gwarp / (126 * 32);
    if (b >= NB) return;

    const int delta1 = d1i - 31;
    const int delta2 = half * 32 + lane - 31;
    const bool lane_ok = (delta2 <= 31);

    const int di = (n & 4) ? 1 : -1;
    const int dj = (n & 2) ? 1 : -1;
    const int dk = (n & 1) ? 1 : -1;

    const int stride = di * 1024 + dj * 32 + dk;
    const int i0 = (di > 0) ? 0 : 31;
    const int j0 = (dj > 0) ? -delta1 : 31 + delta1;
    const int k0 = (dk > 0) ? -delta2 : 31 + delta2;
    const int base = i0 * 1024 + j0 * 32 + k0;

    const int mlo = (delta1 > 0) ? delta1 : 0;
    const int mhi = (delta1 < 0) ? 31 + delta1 : 31;

    const size_t colb = (size_t)b * NSP;
    float* hbp      = g_C + (size_t)(n * 96 +  0 + c) * NROW + colb;
    const float* zp = g_C + (size_t)(n * 96 + 32 + c) * NROW + colb;
    const float* sp = g_C + (size_t)(n * 96 + 64 + c) * NROW + colb;

    float h = h0v[n * 32 + c];

    // distance-2 software pipeline on (z, hb, s)
    int idx = base + mlo * stride;
    bool act0 = lane_ok && ((unsigned)(mlo - delta2) <= 31u);
    float z0 = 0.f, hb0 = 0.f, s0 = 0.f;
    if (act0) { z0 = zp[idx]; hb0 = hbp[idx]; s0 = sp[idx]; }

    int idx1 = idx + stride;
    bool act1 = (mlo + 1 <= mhi) && lane_ok && ((unsigned)(mlo + 1 - delta2) <= 31u);
    float z1 = 0.f, hb1 = 0.f, s1 = 0.f;
    if (act1) { z1 = zp[idx1]; hb1 = hbp[idx1]; s1 = sp[idx1]; }

    for (int m = mlo; m <= mhi; ++m) {
        const int idx2 = idx1 + stride;
        bool act2 = (m + 2 <= mhi) && lane_ok && ((unsigned)(m + 2 - delta2) <= 31u);
        float z2 = 0.f, hb2 = 0.f, s2 = 0.f;
        if (act2) { z2 = zp[idx2]; hb2 = hbp[idx2]; s2 = sp[idx2]; }

        if (act0) {
            h = fmaf(z0, hb0 - h, h);
            hbp[idx] = h * s0;
        }
        idx = idx1; idx1 = idx2;
        act0 = act1; z0 = z1; hb0 = hb1; s0 = s1;
        act1 = act2; z1 = z2; hb1 = hb2; s1 = s2;
    }
}

// ---------------- 5) reduce (float4) -----------------------------------------
__global__ void reduce_kernel(float* __restrict__ out)
{
    const int e4 = blockIdx.x * 256 + threadIdx.x;
    const int b = e4 >> 18;
    const int c = (e4 >> 13) & 31;
    const int sp4 = e4 & 8191;
    const size_t col = ((size_t)b * NSP + sp4 * 4);
    float4 acc = make_float4(0.f, 0.f, 0.f, 0.f);
#pragma unroll
    for (int n = 0; n < 8; ++n) {
        float4 v = *(const float4*)(g_C + (size_t)(n * 96 + c) * NROW + col);
        acc.x += v.x; acc.y += v.y; acc.z += v.z; acc.w += v.w;
    }
    *(float4*)(out + (((size_t)b * 32 + c) * NSP + sp4 * 4)) = acc;
}

// ---------------- launch -------------------------------------------------------
extern "C" void kernel_launch(void* const* d_in, const int* in_sizes, int n_in,
                              void* d_out, int out_size)
{
    const float* x   = (const float*)d_in[0];
    const float* Wh  = (const float*)d_in[1];
    const float* bh  = (const float*)d_in[2];
    const float* Wz  = (const float*)d_in[3];
    const float* bz  = (const float*)d_in[4];
    const float* Ws  = (const float*)d_in[5];
    const float* bs  = (const float*)d_in[6];
    const float* h0v = (const float*)d_in[7];
    float* out = (float*)d_out;

    cudaFuncSetAttribute(im2col_kernel, cudaFuncAttributeMaxDynamicSharedMemorySize, I2C_SMEM);
    cudaFuncSetAttribute(gemm_kernel,   cudaFuncAttributeMaxDynamicSharedMemorySize, GEMM_SMEM);

    wprep_kernel<<<MTOT, 256>>>(Wh, bh, Wz, bz, Ws, bs);
    im2col_kernel<<<2048, 256, I2C_SMEM>>>(x);
    gemm_kernel<<<dim3(6, 256), 256, GEMM_SMEM>>>();
    scan_kernel<<<dim3(1008, 8), 256>>>(h0v);
    reduce_kernel<<<2048, 256>>>(out);
}

// round 9
// speedup vs baseline: 1.2420x; 1.2420x over previous
#include <cuda_runtime.h>
#include <cuda_fp16.h>
#include <cstdint>

// ===========================================================================
// GRUConv3d, single-pass fp16 HMMA GEMM (R6 config: 128x128 block, 32x64 warp,
// 3-stage cp.async, 2 CTAs/SM) + fp16 intermediate planes (g_Ch) to halve
// DRAM traffic in GEMM epilogue / scan / reduce.
// ===========================================================================

#define NB 2
#define NSP 32768
#define NROW 65536
#define KDIM 864            // 32ci * 27taps = 54 * 16
#define MTOT 768            // 8 dir * 3 gate * 32 co

__device__ __align__(16) __half g_Bh[(size_t)NROW * KDIM];
__device__ __align__(16) __half g_Wh[(size_t)MTOT * KDIM];
__device__ __align__(16) __half g_Ch[(size_t)MTOT * NROW];
__device__ float                g_bias[MTOT];

// ---------------- helpers ---------------------------------------------------
__device__ __forceinline__ uint32_t smem_u32(const void* p) {
    uint32_t a;
    asm("{ .reg .u64 t; cvta.to.shared.u64 t, %1; cvt.u32.u64 %0, t; }" : "=r"(a) : "l"(p));
    return a;
}
__device__ __forceinline__ void cp16(uint32_t dst, const void* src) {
    asm volatile("cp.async.cg.shared.global [%0], [%1], 16;" :: "r"(dst), "l"(src));
}
#define CP_COMMIT() asm volatile("cp.async.commit_group;" ::: "memory")
#define CP_WAIT(n)  asm volatile("cp.async.wait_group %0;" :: "n"(n) : "memory")

#define LDSM4(r, a) \
    asm volatile("ldmatrix.sync.aligned.m8n8.x4.shared.b16 {%0,%1,%2,%3}, [%4];" \
                 : "=r"((r)[0]), "=r"((r)[1]), "=r"((r)[2]), "=r"((r)[3]) : "r"(a))

#define MMA16816(c, a, b0, b1) \
    asm volatile("mma.sync.aligned.m16n8k16.row.col.f32.f16.f16.f32 " \
                 "{%0,%1,%2,%3}, {%4,%5,%6,%7}, {%8,%9}, {%0,%1,%2,%3};" \
                 : "+f"((c)[0]), "+f"((c)[1]), "+f"((c)[2]), "+f"((c)[3]) \
                 : "r"((a)[0]), "r"((a)[1]), "r"((a)[2]), "r"((a)[3]), \
                   "r"(b0), "r"(b1))

// ---------------- 1) weight prep --------------------------------------------
__global__ void wprep_kernel(const float* __restrict__ Wh, const float* __restrict__ bh,
                             const float* __restrict__ Wz, const float* __restrict__ bz,
                             const float* __restrict__ Ws, const float* __restrict__ bs)
{
    const int m = blockIdx.x;
    const int n = m / 96, r = m % 96, g = r >> 5, co = r & 31;
    const float* Wp = (g == 0) ? Wh : ((g == 1) ? Wz : Ws);
    const float* bp = (g == 0) ? bh : ((g == 1) ? bz : bs);
    if (threadIdx.x == 0) g_bias[m] = bp[n * 32 + co];
    for (int k = threadIdx.x; k < KDIM; k += blockDim.x) {
        int ci = k / 27, t = k % 27;
        g_Wh[(size_t)m * KDIM + k] =
            __float2half(Wp[((n * 32 + co) * 32 + ci) * 27 + t]);
    }
}

// ---------------- 2) im2col --------------------------------------------------
#define I2C_STRIDE 904
#define I2C_SMEM (32 * I2C_STRIDE * 2)
__global__ void __launch_bounds__(256)
im2col_kernel(const float* __restrict__ x)
{
    extern __shared__ __half sm2[];
    const int tid = threadIdx.x, lane = tid & 31, wi = tid >> 5;
    const int bid = blockIdx.x;
    const int b = bid >> 10, d = (bid >> 5) & 31, h = bid & 31;

    for (int k = wi; k < KDIM; k += 8) {
        int ci = k / 27, t = k % 27;
        int td = t / 9, th = (t % 9) / 3, tw = t % 3;
        int gd = d + td - 1, gh = h + th - 1, gw = lane + tw - 1;
        float v = 0.f;
        if (gd >= 0 && gd < 32 && gh >= 0 && gh < 32 && gw >= 0 && gw < 32)
            v = x[(((b * 32 + ci) * 32 + gd) * 32 + gh) * 32 + gw];
        sm2[lane * I2C_STRIDE + k] = __float2half(v);
    }
    __syncthreads();

    const size_t row0 = (size_t)b * NSP + d * 1024 + h * 32;
    const uint4* smv = (const uint4*)sm2;
    uint4* gv = (uint4*)(g_Bh + row0 * KDIM);
    const int KV = KDIM / 8;
    for (int idx = tid; idx < 32 * KV; idx += 256) {
        int w = idx / KV, kv = idx % KV;
        gv[(size_t)w * KV + kv] = smv[w * (I2C_STRIDE / 8) + kv];
    }
}

// ---------------- 3) GEMM (HMMA fp16, 128x128 tile, 3-stage, K chunks of 32) -
#define ASTR_B 80
#define REG_B_OFF 10240
#define STAGE_B 20480
#define NSTG 3
#define GEMM_SMEM (NSTG * STAGE_B)
#define NKC (KDIM / 32)                      // 27

__global__ void __launch_bounds__(256, 2)
gemm_kernel()
{
    extern __shared__ __align__(16) char sm[];
    const int tid = threadIdx.x, lane = tid & 31, wid = tid >> 5;
    const int m0 = blockIdx.x * 128;
    const size_t n0 = (size_t)blockIdx.y * 128;
    const int wm = wid & 3, wn = wid >> 2;
    const uint32_t sbase = smem_u32(sm);

    const char* gA = (const char*)g_Wh + (size_t)m0 * (KDIM * 2);
    const char* gB = (const char*)g_Bh + n0 * (KDIM * 2);

    float acc[2][8][4];
#pragma unroll
    for (int i = 0; i < 2; ++i)
#pragma unroll
        for (int j = 0; j < 8; ++j)
#pragma unroll
            for (int q = 0; q < 4; ++q) acc[i][j][q] = 0.f;

    const int a_row = lane & 15;
    const int a_k8  = (lane >> 4) << 3;
    const int b_row = wn * 64 + (lane & 7) + ((lane >> 4) << 3);
    const int b_k8  = ((lane >> 3) & 1) << 3;

    auto load_stage = [&](int kc, int s) {
        const int koff = kc * 64;
        const uint32_t st = sbase + s * STAGE_B;
        for (int i = tid; i < 512; i += 256) {
            int r = i >> 2, c = (i & 3) << 4;
            uint32_t d = st + r * ASTR_B + c;
            size_t go = (size_t)r * (KDIM * 2) + koff + c;
            cp16(d, gA + go);
            cp16(d + REG_B_OFF, gB + go);
        }
        CP_COMMIT();
    };

    auto compute = [&](int s) {
        const uint32_t st = sbase + s * STAGE_B;
#pragma unroll
        for (int ks = 0; ks < 2; ++ks) {
            uint32_t A[2][4], B[4][4];
#pragma unroll
            for (int mt2 = 0; mt2 < 2; ++mt2) {
                uint32_t a = st + (wm * 32 + mt2 * 16 + a_row) * ASTR_B
                               + (ks * 16 + a_k8) * 2;
                LDSM4(A[mt2], a);
            }
#pragma unroll
            for (int bt = 0; bt < 4; ++bt) {
                uint32_t a = st + REG_B_OFF + (b_row + bt * 16) * ASTR_B
                               + (ks * 16 + b_k8) * 2;
                LDSM4(B[bt], a);
            }
#pragma unroll
            for (int mt2 = 0; mt2 < 2; ++mt2)
#pragma unroll
                for (int nt8 = 0; nt8 < 8; ++nt8) {
                    const uint32_t* bb = &B[nt8 >> 1][(nt8 & 1) * 2];
                    MMA16816(acc[mt2][nt8], A[mt2], bb[0], bb[1]);
                }
        }
    };

    load_stage(0, 0);
    load_stage(1, 1);
    int s = 0;
    for (int kc = 0; kc < NKC; ++kc) {
        CP_WAIT(1);
        __syncthreads();
        if (kc + 2 < NKC) {
            int s2 = s + 2; if (s2 >= NSTG) s2 -= NSTG;
            load_stage(kc + 2, s2);
        }
        compute(s);
        if (++s == NSTG) s = 0;
    }

    // epilogue: bias + sigmoid for z/s gates, store fp16
    const int rgrp = lane >> 2, cpair = lane & 3;
#pragma unroll
    for (int mt2 = 0; mt2 < 2; ++mt2) {
        const int mA = m0 + wm * 32 + mt2 * 16 + rgrp;
        const bool gate = ((mA >> 5) % 3) != 0;
        const float biasA = g_bias[mA];
        const float biasB = g_bias[mA + 8];
#pragma unroll
        for (int nt8 = 0; nt8 < 8; ++nt8) {
            size_t col = n0 + wn * 64 + nt8 * 8 + cpair * 2;
            float v0 = acc[mt2][nt8][0] + biasA;
            float v1 = acc[mt2][nt8][1] + biasA;
            float v2 = acc[mt2][nt8][2] + biasB;
            float v3 = acc[mt2][nt8][3] + biasB;
            if (gate) {
                v0 = 1.f / (1.f + __expf(-v0));
                v1 = 1.f / (1.f + __expf(-v1));
                v2 = 1.f / (1.f + __expf(-v2));
                v3 = 1.f / (1.f + __expf(-v3));
            }
            *(__half2*)(g_Ch + (size_t)mA * NROW + col) =
                __floats2half2_rn(v0, v1);
            *(__half2*)(g_Ch + (size_t)(mA + 8) * NROW + col) =
                __floats2half2_rn(v2, v3);
        }
    }
}

// ---------------- 4) scan (all dirs, distance-1 pipeline, fp16 planes) -------
__global__ void scan_kernel(const float* __restrict__ h0v)
{
    const int gwarp = (blockIdx.x * blockDim.x + threadIdx.x) >> 5;
    const int lane  = threadIdx.x & 31;
    const int n     = blockIdx.y;
    const int half  = gwarp & 1;
    const int d1i   = (gwarp >> 1) % 63;
    const int c     = (gwarp / 126) % 32;
    const int b     = gwarp / (126 * 32);
    if (b >= NB) return;

    const int delta1 = d1i - 31;
    const int delta2 = half * 32 + lane - 31;
    const bool lane_ok = (delta2 <= 31);

    const int di = (n & 4) ? 1 : -1;
    const int dj = (n & 2) ? 1 : -1;
    const int dk = (n & 1) ? 1 : -1;

    const int stride = di * 1024 + dj * 32 + dk;
    const int i0 = (di > 0) ? 0 : 31;
    const int j0 = (dj > 0) ? -delta1 : 31 + delta1;
    const int k0 = (dk > 0) ? -delta2 : 31 + delta2;
    const int base = i0 * 1024 + j0 * 32 + k0;

    const int mlo = (delta1 > 0) ? delta1 : 0;
    const int mhi = (delta1 < 0) ? 31 + delta1 : 31;

    const size_t colb = (size_t)b * NSP;
    __half* hbp       = g_Ch + (size_t)(n * 96 +  0 + c) * NROW + colb;
    const __half* zp  = g_Ch + (size_t)(n * 96 + 32 + c) * NROW + colb;
    const __half* sp  = g_Ch + (size_t)(n * 96 + 64 + c) * NROW + colb;

    float h = h0v[n * 32 + c];

    int idx = base + mlo * stride;
    bool act = lane_ok && ((unsigned)(mlo - delta2) <= 31u);
    float z = 0.f, hb = 0.f, s = 0.f;
    if (act) { z = __half2float(zp[idx]); hb = __half2float(hbp[idx]); s = __half2float(sp[idx]); }

    for (int m = mlo; m <= mhi; ++m) {
        const int nidx = idx + stride;
        const bool last = (m == mhi);
        bool nact = !last && lane_ok && ((unsigned)(m + 1 - delta2) <= 31u);
        float nz = 0.f, nhb = 0.f, ns = 0.f;
        if (nact) { nz = __half2float(zp[nidx]); nhb = __half2float(hbp[nidx]); ns = __half2float(sp[nidx]); }

        if (act) {
            h = fmaf(z, hb - h, h);          // z*hb + (1-z)*h
            hbp[idx] = __float2half(h * s);  // contrib in place of hb
        }
        idx = nidx; act = nact; z = nz; hb = nhb; s = ns;
    }
}

// ---------------- 5) reduce (fp16 in, fp32 out, 4 elems/thread) --------------
__global__ void reduce_kernel(float* __restrict__ out)
{
    const int e4 = blockIdx.x * 256 + threadIdx.x;   // 524288
    const int b = e4 >> 18;
    const int c = (e4 >> 13) & 31;
    const int sp4 = e4 & 8191;
    const size_t col = ((size_t)b * NSP + sp4 * 4);
    float2 a01 = make_float2(0.f, 0.f), a23 = make_float2(0.f, 0.f);
#pragma unroll
    for (int n = 0; n < 8; ++n) {
        const __half2* p = (const __half2*)(g_Ch + (size_t)(n * 96 + c) * NROW + col);
        float2 v0 = __half22float2(p[0]);
        float2 v1 = __half22float2(p[1]);
        a01.x += v0.x; a01.y += v0.y; a23.x += v1.x; a23.y += v1.y;
    }
    float4 r = make_float4(a01.x, a01.y, a23.x, a23.y);
    *(float4*)(out + (((size_t)b * 32 + c) * NSP + sp4 * 4)) = r;
}

// ---------------- launch -------------------------------------------------------
extern "C" void kernel_launch(void* const* d_in, const int* in_sizes, int n_in,
                              void* d_out, int out_size)
{
    const float* x   = (const float*)d_in[0];
    const float* Wh  = (const float*)d_in[1];
    const float* bh  = (const float*)d_in[2];
    const float* Wz  = (const float*)d_in[3];
    const float* bz  = (const float*)d_in[4];
    const float* Ws  = (const float*)d_in[5];
    const float* bs  = (const float*)d_in[6];
    const float* h0v = (const float*)d_in[7];
    float* out = (float*)d_out;

    cudaFuncSetAttribute(im2col_kernel, cudaFuncAttributeMaxDynamicSharedMemorySize, I2C_SMEM);
    cudaFuncSetAttribute(gemm_kernel,   cudaFuncAttributeMaxDynamicSharedMemorySize, GEMM_SMEM);

    wprep_kernel<<<MTOT, 256>>>(Wh, bh, Wz, bz, Ws, bs);
    im2col_kernel<<<2048, 256, I2C_SMEM>>>(x);
    gemm_kernel<<<dim3(6, 512), 256, GEMM_SMEM>>>();
    scan_kernel<<<dim3(1008, 8), 256>>>(h0v);
    reduce_kernel<<<2048, 256>>>(out);
}